// round 10
// baseline (speedup 1.0000x reference)
#include <cuda_runtime.h>
#include <cuda_bf16.h>

// Elementwise clamp to [-0.5f, 0.5f] of n fp32 elements.
// HBM-streaming: float4 vectorized, 8 independent 128b loads front-batched per
// thread (MLP=8, groups DRAM reads vs writes to cut bus turnaround),
// streaming cache hints, 32-bit indexing.

#define LO (-0.5f)
#define HI ( 0.5f)

__device__ __forceinline__ float4 clamp4(float4 v) {
    v.x = fminf(fmaxf(v.x, LO), HI);
    v.y = fminf(fmaxf(v.y, LO), HI);
    v.z = fminf(fmaxf(v.z, LO), HI);
    v.w = fminf(fmaxf(v.w, LO), HI);
    return v;
}

// Exact-coverage vectorized path: grid*THREADS*VPT == n4 exactly.
// Accesses are warp-coalesced; per-thread vectors are grid-strided.
template <int VPT>
__global__ void __launch_bounds__(256)
clip_vec4_kernel(const float4* __restrict__ in, float4* __restrict__ out) {
    unsigned stride = gridDim.x * blockDim.x;
    unsigned base = blockIdx.x * blockDim.x + threadIdx.x;

    float4 v[VPT];
#pragma unroll
    for (int i = 0; i < VPT; i++) {
        v[i] = __ldcs(in + base + (unsigned)i * stride);
    }
#pragma unroll
    for (int i = 0; i < VPT; i++) {
        __stcs(out + base + (unsigned)i * stride, clamp4(v[i]));
    }
}

// Grid-stride scalar fallback (remainders / non-vectorizable sizes).
__global__ void clip_scalar_kernel(const float* __restrict__ in,
                                   float* __restrict__ out, long long n) {
    long long stride = (long long)gridDim.x * blockDim.x;
    for (long long i = (long long)blockIdx.x * blockDim.x + threadIdx.x; i < n; i += stride) {
        out[i] = fminf(fmaxf(__ldcs(in + i), LO), HI);
    }
}

extern "C" void kernel_launch(void* const* d_in, const int* in_sizes, int n_in,
                              void* d_out, int out_size) {
    const float* x = (const float*)d_in[0];
    float* out = (float*)d_out;
    long long n = (long long)in_sizes[0];

    constexpr int THREADS = 256;
    constexpr int VPT = 8;  // float4 vectors per thread
    const long long chunk4 = (long long)THREADS * VPT;  // float4s per block

    if (n % 4 == 0 && (n / 4) < (1LL << 31)) {
        long long n4 = n / 4;
        long long full = n4 / chunk4;
        if (full > 0) {
            clip_vec4_kernel<VPT><<<(unsigned)full, THREADS>>>(
                (const float4*)x, (float4*)out);
        }
        long long done = full * chunk4 * 4;  // elements covered
        long long rem = n - done;
        if (rem > 0) {
            int blocks = (int)((rem + THREADS - 1) / THREADS);
            if (blocks > 65535) blocks = 65535;
            clip_scalar_kernel<<<blocks, THREADS>>>(x + done, out + done, rem);
        }
        return;
    }

    // Fully scalar fallback.
    int blocks = (int)((n + THREADS - 1) / THREADS);
    if (blocks > 65535) blocks = 65535;
    clip_scalar_kernel<<<blocks, THREADS>>>(x, out, n);
}

// round 14
// speedup vs baseline: 1.0016x; 1.0016x over previous
#include <cuda_runtime.h>
#include <cuda_bf16.h>

// Elementwise clamp to [-0.5f, 0.5f] of n fp32 elements.
// HBM-streaming: float4 vectorized, 8 independent 128b loads front-batched per
// thread (MLP=8, groups DRAM reads vs writes to cut bus turnaround),
// streaming cache hints, 32-bit indexing.

#define LO (-0.5f)
#define HI ( 0.5f)

__device__ __forceinline__ float4 clamp4(float4 v) {
    v.x = fminf(fmaxf(v.x, LO), HI);
    v.y = fminf(fmaxf(v.y, LO), HI);
    v.z = fminf(fmaxf(v.z, LO), HI);
    v.w = fminf(fmaxf(v.w, LO), HI);
    return v;
}

// Exact-coverage vectorized path: grid*THREADS*VPT == n4 exactly.
// Accesses are warp-coalesced; per-thread vectors are grid-strided.
template <int VPT>
__global__ void __launch_bounds__(256)
clip_vec4_kernel(const float4* __restrict__ in, float4* __restrict__ out) {
    unsigned stride = gridDim.x * blockDim.x;
    unsigned base = blockIdx.x * blockDim.x + threadIdx.x;

    float4 v[VPT];
#pragma unroll
    for (int i = 0; i < VPT; i++) {
        v[i] = __ldcs(in + base + (unsigned)i * stride);
    }
#pragma unroll
    for (int i = 0; i < VPT; i++) {
        __stcs(out + base + (unsigned)i * stride, clamp4(v[i]));
    }
}

// Grid-stride scalar fallback (remainders / non-vectorizable sizes).
__global__ void clip_scalar_kernel(const float* __restrict__ in,
                                   float* __restrict__ out, long long n) {
    long long stride = (long long)gridDim.x * blockDim.x;
    for (long long i = (long long)blockIdx.x * blockDim.x + threadIdx.x; i < n; i += stride) {
        out[i] = fminf(fmaxf(__ldcs(in + i), LO), HI);
    }
}

extern "C" void kernel_launch(void* const* d_in, const int* in_sizes, int n_in,
                              void* d_out, int out_size) {
    const float* x = (const float*)d_in[0];
    float* out = (float*)d_out;
    long long n = (long long)in_sizes[0];

    constexpr int THREADS = 256;
    constexpr int VPT = 8;  // float4 vectors per thread
    const long long chunk4 = (long long)THREADS * VPT;  // float4s per block

    if (n % 4 == 0 && (n / 4) < (1LL << 31)) {
        long long n4 = n / 4;
        long long full = n4 / chunk4;
        if (full > 0) {
            clip_vec4_kernel<VPT><<<(unsigned)full, THREADS>>>(
                (const float4*)x, (float4*)out);
        }
        long long done = full * chunk4 * 4;  // elements covered
        long long rem = n - done;
        if (rem > 0) {
            int blocks = (int)((rem + THREADS - 1) / THREADS);
            if (blocks > 65535) blocks = 65535;
            clip_scalar_kernel<<<blocks, THREADS>>>(x + done, out + done, rem);
        }
        return;
    }

    // Fully scalar fallback.
    int blocks = (int)((n + THREADS - 1) / THREADS);
    if (blocks > 65535) blocks = 65535;
    clip_scalar_kernel<<<blocks, THREADS>>>(x, out, n);
}